// round 14
// baseline (speedup 1.0000x reference)
#include <cuda_runtime.h>
#include <cuda_bf16.h>
#include <cstdint>
#include <math.h>

// Problem constants
constexpr int cB  = 2;
constexpr int cS  = 2048;
constexpr int cD  = 1024;
constexpr int cH  = 16;
constexpr int cHD = 64;
constexpr int cM  = cB * cS;  // 4096 rows

// ---------------------------------------------------------------------------
// Scratch (allocation-free rule: __device__ globals)
// ---------------------------------------------------------------------------
__device__ __nv_bfloat16 g_xh[cM * cD], g_xl[cM * cD];
__device__ __nv_bfloat16 g_qh[cM * cD], g_ql[cM * cD];
__device__ __nv_bfloat16 g_kh[cM * cD], g_kl[cM * cD];
__device__ __nv_bfloat16 g_vh[cM * cD], g_vl[cM * cD];
__device__ __nv_bfloat16 g_ch[cM * cD], g_cl[cM * cD];
__device__ __nv_bfloat16 g_Wqh[cD * cD], g_Wql[cD * cD];
__device__ __nv_bfloat16 g_Wkh[cD * cD], g_Wkl[cD * cD];
__device__ __nv_bfloat16 g_Wvh[cD * cD], g_Wvl[cD * cD];
__device__ __nv_bfloat16 g_Woh[cD * cD], g_Wol[cD * cD];

// Single shared-memory symbol for all dynamic-smem kernels
extern __shared__ char smem_raw[];

// ---------------------------------------------------------------------------
// Helpers (sm_80-era features only: ldmatrix, mma.sync bf16, cp.async)
// ---------------------------------------------------------------------------
__device__ __forceinline__ uint32_t smem_to_u32(const void* smem_ptr) {
    uint32_t addr;
    asm("{ .reg .u64 tmp; cvta.to.shared.u64 tmp, %1; cvt.u32.u64 %0, tmp; }"
        : "=r"(addr) : "l"(smem_ptr));
    return addr;
}

__device__ __forceinline__ void cp_async16(uint32_t dst, const void* src) {
    asm volatile("cp.async.cg.shared.global [%0], [%1], 16;" :: "r"(dst), "l"(src));
}
#define CP_COMMIT() asm volatile("cp.async.commit_group;" ::: "memory")
#define CP_WAIT0()  asm volatile("cp.async.wait_group 0;"  ::: "memory")

__device__ __forceinline__ void ldmx4(uint32_t* d, uint32_t addr) {
    asm volatile("ldmatrix.sync.aligned.m8n8.x4.shared.b16 {%0,%1,%2,%3}, [%4];"
                 : "=r"(d[0]), "=r"(d[1]), "=r"(d[2]), "=r"(d[3]) : "r"(addr));
}
__device__ __forceinline__ void ldmx4t(uint32_t* d, uint32_t addr) {
    asm volatile("ldmatrix.sync.aligned.m8n8.x4.trans.shared.b16 {%0,%1,%2,%3}, [%4];"
                 : "=r"(d[0]), "=r"(d[1]), "=r"(d[2]), "=r"(d[3]) : "r"(addr));
}

__device__ __forceinline__ void mma16816(float* c, const uint32_t* a,
                                         uint32_t b0, uint32_t b1) {
    asm volatile(
        "mma.sync.aligned.m16n8k16.row.col.f32.bf16.bf16.f32 "
        "{%0,%1,%2,%3}, {%4,%5,%6,%7}, {%8,%9}, {%0,%1,%2,%3};"
        : "+f"(c[0]), "+f"(c[1]), "+f"(c[2]), "+f"(c[3])
        : "r"(a[0]), "r"(a[1]), "r"(a[2]), "r"(a[3]), "r"(b0), "r"(b1));
}

__device__ __forceinline__ float exp2a(float x) {
    float y;
    asm("ex2.approx.f32 %0, %1;" : "=f"(y) : "f"(x));
    return y;
}

// pack two fp32 into bf16x2 hi part, return lo residual bf16x2 via out-param
__device__ __forceinline__ uint32_t packsplit(float p0, float p1, uint32_t& lo) {
    __nv_bfloat16 h0 = __float2bfloat16(p0);
    __nv_bfloat16 h1 = __float2bfloat16(p1);
    __nv_bfloat162 hv; hv.x = h0; hv.y = h1;
    __nv_bfloat162 lv;
    lv.x = __float2bfloat16(p0 - __bfloat162float(h0));
    lv.y = __float2bfloat16(p1 - __bfloat162float(h1));
    lo = *(uint32_t*)&lv;
    return *(uint32_t*)&hv;
}

// ---------------------------------------------------------------------------
// bf16-split (Ootomo) mma.sync GEMM core: C = (Ah+Al)[M,K] @ (Bh+Bl)[N,K]^T
// 128x128x32 CTA tile, 256 threads (8 warps, 4x2), warp tile 32x64,
// 2-stage cp.async, __launch_bounds__(256,2) -> 2 CTAs/SM (16 warps/SM).
// ---------------------------------------------------------------------------
constexpr int BKg = 32;
constexpr int LDT = BKg + 8;                    // 40 bf16 per smem row
constexpr int TILE_E  = 128 * LDT;              // 5120 elems
constexpr int STAGE_E = 4 * TILE_E;             // Ah, Al, Bh, Bl
constexpr int GEMM_SMEM = 2 * STAGE_E * 2;      // 81920 bytes
constexpr int NCH = cD / BKg;                   // 32 k-chunks

template <bool SPLIT_OUT>
__device__ __forceinline__ void gemm_core(
    const __nv_bfloat16* __restrict__ Ah, const __nv_bfloat16* __restrict__ Al,
    const __nv_bfloat16* __restrict__ Bh, const __nv_bfloat16* __restrict__ Bl,
    const float* __restrict__ bias, float* __restrict__ C,
    __nv_bfloat16* __restrict__ Ch, __nv_bfloat16* __restrict__ Cl,
    int m0, int n0)
{
    const uint32_t sbase = smem_to_u32(smem_raw);
    const int tid = threadIdx.x, wid = tid >> 5, lane = tid & 31;

    const int r0v = tid >> 2, s0v = tid & 3;          // vector tid
    const int r1v = (tid + 256) >> 2;                 // vector tid+256

    const __nv_bfloat16* gAh = Ah + (size_t)m0 * cD;
    const __nv_bfloat16* gAl = Al + (size_t)m0 * cD;
    const __nv_bfloat16* gBh = Bh + (size_t)n0 * cD;
    const __nv_bfloat16* gBl = Bl + (size_t)n0 * cD;

    auto load_stage = [&](int chunk, int stage) {
        const int k0 = chunk * BKg;
        const uint32_t sb = sbase + (uint32_t)stage * STAGE_E * 2;
        const uint32_t o0 = (uint32_t)(r0v * LDT + s0v * 8) * 2;
        const uint32_t o1 = (uint32_t)(r1v * LDT + s0v * 8) * 2;
        const size_t g0 = (size_t)r0v * cD + k0 + s0v * 8;
        const size_t g1 = (size_t)r1v * cD + k0 + s0v * 8;
        cp_async16(sb + o0,                  gAh + g0);
        cp_async16(sb + o1,                  gAh + g1);
        cp_async16(sb + TILE_E * 2 + o0,     gAl + g0);
        cp_async16(sb + TILE_E * 2 + o1,     gAl + g1);
        cp_async16(sb + 2 * TILE_E * 2 + o0, gBh + g0);
        cp_async16(sb + 2 * TILE_E * 2 + o1, gBh + g1);
        cp_async16(sb + 3 * TILE_E * 2 + o0, gBl + g0);
        cp_async16(sb + 3 * TILE_E * 2 + o1, gBl + g1);
        CP_COMMIT();
    };

    // Warp tiling: 4 (m) x 2 (n) warps; warp tile 32x64
    const int mb = (wid >> 1) * 32;
    const int nb = (wid & 1) * 64;
    const int lr  = lane & 7;
    const int sub = lane >> 3;

    float acc[2][8][4];
#pragma unroll
    for (int i = 0; i < 2; i++)
#pragma unroll
        for (int j = 0; j < 8; j++)
#pragma unroll
            for (int q = 0; q < 4; q++) acc[i][j][q] = 0.f;

    load_stage(0, 0);

    for (int i = 0; i < NCH; i++) {
        CP_WAIT0();
        __syncthreads();
        if (i + 1 < NCH) load_stage(i + 1, (i + 1) & 1);

        const uint32_t sb  = sbase + (uint32_t)(i & 1) * STAGE_E * 2;
        const uint32_t sAh = sb;
        const uint32_t sAl = sb + TILE_E * 2;
        const uint32_t sBh = sb + 2 * TILE_E * 2;
        const uint32_t sBl = sb + 3 * TILE_E * 2;

#pragma unroll
        for (int ks = 0; ks < 2; ks++) {
            const int kc = ks * 16 + (sub >> 1) * 8;
            uint32_t ah[2][4], al[2][4];
#pragma unroll
            for (int mf = 0; mf < 2; mf++) {
                const uint32_t off =
                    (uint32_t)((mb + mf * 16 + (sub & 1) * 8 + lr) * LDT + kc) * 2;
                ldmx4(ah[mf], sAh + off);
                ldmx4(al[mf], sAl + off);
            }
#pragma unroll
            for (int p = 0; p < 4; p++) {
                const uint32_t boff =
                    (uint32_t)((nb + p * 16 + (sub & 1) * 8 + lr) * LDT + kc) * 2;
                uint32_t bh[4], bl[4];
                ldmx4(bh, sBh + boff);
                ldmx4(bl, sBl + boff);
#pragma unroll
                for (int mf = 0; mf < 2; mf++) {
                    mma16816(acc[mf][2 * p],     ah[mf], bh[0], bh[2]);
                    mma16816(acc[mf][2 * p + 1], ah[mf], bh[1], bh[3]);
                    mma16816(acc[mf][2 * p],     ah[mf], bl[0], bl[2]);
                    mma16816(acc[mf][2 * p + 1], ah[mf], bl[1], bl[3]);
                    mma16816(acc[mf][2 * p],     al[mf], bh[0], bh[2]);
                    mma16816(acc[mf][2 * p + 1], al[mf], bh[1], bh[3]);
                }
            }
        }
        __syncthreads();
    }

    // Epilogue
    const int er = lane >> 2;
    const int ec = (lane & 3) * 2;
    if (SPLIT_OUT) {
#pragma unroll
        for (int mf = 0; mf < 2; mf++) {
#pragma unroll
            for (int nf = 0; nf < 8; nf++) {
                const int row = m0 + mb + mf * 16 + er;
                const int col = n0 + nb + nf * 8 + ec;
                uint32_t lo, hi;
                hi = packsplit(acc[mf][nf][0], acc[mf][nf][1], lo);
                *(uint32_t*)(Ch + (size_t)row * cD + col) = hi;
                *(uint32_t*)(Cl + (size_t)row * cD + col) = lo;
                hi = packsplit(acc[mf][nf][2], acc[mf][nf][3], lo);
                *(uint32_t*)(Ch + (size_t)(row + 8) * cD + col) = hi;
                *(uint32_t*)(Cl + (size_t)(row + 8) * cD + col) = lo;
            }
        }
    } else {
#pragma unroll
        for (int mf = 0; mf < 2; mf++) {
#pragma unroll
            for (int nf = 0; nf < 8; nf++) {
                const int row = m0 + mb + mf * 16 + er;
                const int col = n0 + nb + nf * 8 + ec;
                const float b0 = bias[col], b1 = bias[col + 1];
                float2 v0 = make_float2(acc[mf][nf][0] + b0, acc[mf][nf][1] + b1);
                float2 v1 = make_float2(acc[mf][nf][2] + b0, acc[mf][nf][3] + b1);
                *(float2*)(C + (size_t)row * cD + col)       = v0;
                *(float2*)(C + (size_t)(row + 8) * cD + col) = v1;
            }
        }
    }
}

// Fused QKV projection: grid (24, 32); blockIdx.x>>3 selects {Wq,Wk,Wv}
__global__ void __launch_bounds__(256, 2) gemm_qkv_kernel(
    const __nv_bfloat16* __restrict__ xh, const __nv_bfloat16* __restrict__ xl,
    const __nv_bfloat16* __restrict__ wqh, const __nv_bfloat16* __restrict__ wql,
    const __nv_bfloat16* __restrict__ wkh, const __nv_bfloat16* __restrict__ wkl,
    const __nv_bfloat16* __restrict__ wvh, const __nv_bfloat16* __restrict__ wvl,
    __nv_bfloat16* __restrict__ qh, __nv_bfloat16* __restrict__ ql,
    __nv_bfloat16* __restrict__ kh, __nv_bfloat16* __restrict__ kl,
    __nv_bfloat16* __restrict__ vh, __nv_bfloat16* __restrict__ vl)
{
    const int sel = blockIdx.x >> 3;
    const int n0 = (blockIdx.x & 7) * 128;
    const int m0 = blockIdx.y * 128;
    const __nv_bfloat16 *Bh, *Bl;
    __nv_bfloat16 *Oh, *Ol;
    if (sel == 0)      { Bh = wqh; Bl = wql; Oh = qh; Ol = ql; }
    else if (sel == 1) { Bh = wkh; Bl = wkl; Oh = kh; Ol = kl; }
    else               { Bh = wvh; Bl = wvl; Oh = vh; Ol = vl; }
    gemm_core<true>(xh, xl, Bh, Bl, nullptr, nullptr, Oh, Ol, m0, n0);
}

// Output projection: fp32 + bias
__global__ void __launch_bounds__(256, 2) gemm_out_kernel(
    const __nv_bfloat16* __restrict__ ch, const __nv_bfloat16* __restrict__ cl,
    const __nv_bfloat16* __restrict__ woh, const __nv_bfloat16* __restrict__ wol,
    const float* __restrict__ bias, float* __restrict__ out)
{
    gemm_core<false>(ch, cl, woh, wol, bias, out, nullptr, nullptr,
                     blockIdx.y * 128, blockIdx.x * 128);
}

// ---------------------------------------------------------------------------
// fp32 -> bf16 hi/lo split (elementwise, vectorized)
// ---------------------------------------------------------------------------
__global__ void __launch_bounds__(256) split_kernel(
    const float4* __restrict__ a, __nv_bfloat16* __restrict__ hi,
    __nv_bfloat16* __restrict__ lo, int n4)
{
    int i = blockIdx.x * blockDim.x + threadIdx.x;
    if (i >= n4) return;
    float4 v = a[i];
    uint32_t l01, l23;
    uint32_t h01 = packsplit(v.x, v.y, l01);
    uint32_t h23 = packsplit(v.z, v.w, l23);
    ((uint32_t*)hi)[i * 2]     = h01;
    ((uint32_t*)hi)[i * 2 + 1] = h23;
    ((uint32_t*)lo)[i * 2]     = l01;
    ((uint32_t*)lo)[i * 2 + 1] = l23;
}

// ---------------------------------------------------------------------------
// Fused weight transpose + split for all 4 weights (blockIdx.z selects W)
// ---------------------------------------------------------------------------
__global__ void __launch_bounds__(256) tsplit4_kernel(
    const float* __restrict__ Wq, const float* __restrict__ Wk,
    const float* __restrict__ Wv, const float* __restrict__ Wo,
    __nv_bfloat16* __restrict__ qh, __nv_bfloat16* __restrict__ ql,
    __nv_bfloat16* __restrict__ kh, __nv_bfloat16* __restrict__ kl,
    __nv_bfloat16* __restrict__ vh, __nv_bfloat16* __restrict__ vl,
    __nv_bfloat16* __restrict__ oh, __nv_bfloat16* __restrict__ ol)
{
    __shared__ float s[32][33];
    const float* W;
    __nv_bfloat16 *Th, *Tl;
    switch (blockIdx.z) {
        case 0:  W = Wq; Th = qh; Tl = ql; break;
        case 1:  W = Wk; Th = kh; Tl = kl; break;
        case 2:  W = Wv; Th = vh; Tl = vl; break;
        default: W = Wo; Th = oh; Tl = ol; break;
    }
    const int n0 = blockIdx.x * 32;
    const int k0 = blockIdx.y * 32;
    const int tx = threadIdx.x, ty = threadIdx.y;  // 32 x 8
#pragma unroll
    for (int r = 0; r < 32; r += 8)
        s[ty + r][tx] = W[(size_t)(k0 + ty + r) * cD + n0 + tx];
    __syncthreads();
#pragma unroll
    for (int r = 0; r < 32; r += 8) {
        float v = s[tx][ty + r];
        __nv_bfloat16 h = __float2bfloat16(v);
        __nv_bfloat16 l = __float2bfloat16(v - __bfloat162float(h));
        size_t o = (size_t)(n0 + ty + r) * cD + k0 + tx;
        Th[o] = h; Tl[o] = l;
    }
}

// ---------------------------------------------------------------------------
// Tensor-core causal flash attention (bf16 split, fp32 accum).
// __launch_bounds__(256, 2) -> 2 CTAs/SM (16 warps/SM).
// ---------------------------------------------------------------------------
constexpr int ALD = 72;                       // padded row length (bf16 elems)
constexpr int KV_TILE_B = 64 * ALD * 2;       // 9216 bytes
constexpr int KV_STB = 4 * KV_TILE_B;         // stage: Kh,Kl,Vh,Vl = 36864
constexpr int ATTN_SMEM = 2 * KV_STB;         // 73728
constexpr float CQ = 0.18033688011112042f;    // 0.125 * log2(e)

__global__ void __launch_bounds__(256, 2) attn_tc_kernel(
    const __nv_bfloat16* __restrict__ qh_g, const __nv_bfloat16* __restrict__ ql_g,
    const __nv_bfloat16* __restrict__ kh_g, const __nv_bfloat16* __restrict__ kl_g,
    const __nv_bfloat16* __restrict__ vh_g, const __nv_bfloat16* __restrict__ vl_g,
    __nv_bfloat16* __restrict__ ch_g, __nv_bfloat16* __restrict__ cl_g)
{
    const uint32_t sb0 = smem_to_u32(smem_raw);

    const int tid = threadIdx.x, wid = tid >> 5, lane = tid & 31;
    const int qt = (int)gridDim.x - 1 - (int)blockIdx.x;  // big tiles first
    const int h = blockIdx.y, b = blockIdx.z;
    const int qbase = qt * 128 + wid * 16;
    const size_t gb = (size_t)b * cS * cD + (size_t)h * cHD;

    const int vrow = tid >> 3, vseg = tid & 7;
    auto load_kv = [&](int t, int stage) {
        const int k0 = t * 64;
        const uint32_t s = sb0 + stage * KV_STB;
#pragma unroll
        for (int r = 0; r < 2; r++) {
            const int row = vrow + r * 32;
            const size_t g = gb + (size_t)(k0 + row) * cD + vseg * 8;
            const uint32_t so = (uint32_t)(row * ALD + vseg * 8) * 2;
            cp_async16(s + so,                kh_g + g);
            cp_async16(s + KV_TILE_B + so,    kl_g + g);
            cp_async16(s + 2 * KV_TILE_B + so, vh_g + g);
            cp_async16(s + 3 * KV_TILE_B + so, vl_g + g);
        }
    };
    load_kv(0, 0);
    CP_COMMIT();

    // Stage Q tile (hi/lo) into stage-1 region, extract fragments, then the
    // region is recycled for K/V stage 1 (guarded by the t=0 loop sync).
    {
        char* qp = smem_raw + KV_STB;
#pragma unroll
        for (int r = 0; r < 4; r++) {
            const int v = tid + r * 256;          // 0..1023
            const int row = v >> 3, seg = v & 7;
            const size_t g = gb + (size_t)(qt * 128 + row) * cD + seg * 8;
            const uint32_t so = (uint32_t)(row * ALD + seg * 8) * 2;
            *(uint4*)(qp + so)          = *(const uint4*)(qh_g + g);
            *(uint4*)(qp + 18432 + so)  = *(const uint4*)(ql_g + g);
        }
    }
    __syncthreads();
    uint32_t qfh[4][4], qfl[4][4];
    {
        const uint32_t qs = sb0 + KV_STB;
        const int rr = wid * 16 + (lane & 15);
        const int cc = (lane >> 4) * 8;
#pragma unroll
        for (int ks = 0; ks < 4; ks++) {
            const uint32_t off = (uint32_t)(rr * ALD + ks * 16 + cc) * 2;
            ldmx4(qfh[ks], qs + off);
            ldmx4(qfl[ks], qs + 18432 + off);
        }
    }

    float m0 = -1e30f, m1 = -1e30f, l0 = 0.f, l1 = 0.f;
    float out[8][4];
#pragma unroll
    for (int j = 0; j < 8; j++)
#pragma unroll
        for (int q = 0; q < 4; q++) out[j][q] = 0.f;

    const int ntiles = 2 * qt + 2;
    const int sub = lane >> 3, lr = lane & 7;
    const int row_lo = qbase + (lane >> 2);
    const int row_hi = row_lo + 8;

    for (int t = 0; t < ntiles; t++) {
        CP_WAIT0();
        __syncthreads();
        if (t + 1 < ntiles) { load_kv(t + 1, (t + 1) & 1); CP_COMMIT(); }

        const int k0 = t * 64;
        if (k0 <= qbase + 15) {          // any visible keys for this warp
            const uint32_t s = sb0 + (t & 1) * KV_STB;

            // ---- scores: S = Q @ K^T (3-term split) ----
            float sc[8][4];
#pragma unroll
            for (int j = 0; j < 8; j++) {
                sc[j][0] = 0.f; sc[j][1] = 0.f; sc[j][2] = 0.f; sc[j][3] = 0.f;
            }
#pragma unroll
            for (int ks = 0; ks < 4; ks++) {
#pragma unroll
                for (int g = 0; g < 4; g++) {
                    const uint32_t ko = (uint32_t)((g * 16 + (sub & 1) * 8 + lr) * ALD
                                                   + ks * 16 + (sub >> 1) * 8) * 2;
                    uint32_t bh[4], bl[4];
                    ldmx4(bh, s + ko);
                    ldmx4(bl, s + KV_TILE_B + ko);
                    mma16816(sc[2 * g],     qfh[ks], bh[0], bh[2]);
                    mma16816(sc[2 * g + 1], qfh[ks], bh[1], bh[3]);
                    mma16816(sc[2 * g],     qfh[ks], bl[0], bl[2]);
                    mma16816(sc[2 * g + 1], qfh[ks], bl[1], bl[3]);
                    mma16816(sc[2 * g],     qfl[ks], bh[0], bh[2]);
                    mma16816(sc[2 * g + 1], qfl[ks], bh[1], bh[3]);
                }
            }

            // ---- causal mask (diagonal tiles only) ----
            if (k0 + 63 > qbase) {
#pragma unroll
                for (int j = 0; j < 8; j++) {
                    const int c0 = k0 + j * 8 + (lane & 3) * 2;
                    if (c0     > row_lo) sc[j][0] = -1e30f;
                    if (c0 + 1 > row_lo) sc[j][1] = -1e30f;
                    if (c0     > row_hi) sc[j][2] = -1e30f;
                    if (c0 + 1 > row_hi) sc[j][3] = -1e30f;
                }
            }

            // ---- online softmax (raw-score domain, exp2 with CQ) ----
            float mx0 = -1e30f, mx1 = -1e30f;
#pragma unroll
            for (int j = 0; j < 8; j++) {
                mx0 = fmaxf(mx0, fmaxf(sc[j][0], sc[j][1]));
                mx1 = fmaxf(mx1, fmaxf(sc[j][2], sc[j][3]));
            }
            mx0 = fmaxf(mx0, __shfl_xor_sync(0xffffffffu, mx0, 1));
            mx0 = fmaxf(mx0, __shfl_xor_sync(0xffffffffu, mx0, 2));
            mx1 = fmaxf(mx1, __shfl_xor_sync(0xffffffffu, mx1, 1));
            mx1 = fmaxf(mx1, __shfl_xor_sync(0xffffffffu, mx1, 2));
            const float nm0 = fmaxf(m0, mx0), nm1 = fmaxf(m1, mx1);
            const float cr0 = exp2a((m0 - nm0) * CQ);
            const float cr1 = exp2a((m1 - nm1) * CQ);
            m0 = nm0; m1 = nm1;
            l0 *= cr0; l1 *= cr1;
#pragma unroll
            for (int j = 0; j < 8; j++) {
                out[j][0] *= cr0; out[j][1] *= cr0;
                out[j][2] *= cr1; out[j][3] *= cr1;
            }
#pragma unroll
            for (int j = 0; j < 8; j++) {
                sc[j][0] = exp2a((sc[j][0] - m0) * CQ);
                sc[j][1] = exp2a((sc[j][1] - m0) * CQ);
                sc[j][2] = exp2a((sc[j][2] - m1) * CQ);
                sc[j][3] = exp2a((sc[j][3] - m1) * CQ);
                l0 += sc[j][0] + sc[j][1];
                l1 += sc[j][2] + sc[j][3];
            }

            // ---- out += P @ V (3-term split, P split in registers) ----
#pragma unroll
            for (int t2 = 0; t2 < 4; t2++) {
                uint32_t ah[4], al[4];
                ah[0] = packsplit(sc[2 * t2][0],     sc[2 * t2][1],     al[0]);
                ah[1] = packsplit(sc[2 * t2][2],     sc[2 * t2][3],     al[1]);
                ah[2] = packsplit(sc[2 * t2 + 1][0], sc[2 * t2 + 1][1], al[2]);
                ah[3] = packsplit(sc[2 * t2 + 1][2], sc[2 * t2 + 1][3], al[3]);
#pragma unroll
                for (int g = 0; g < 4; g++) {
                    const uint32_t vo = (uint32_t)((t2 * 16 + (sub & 1) * 8 + lr) * ALD
                                                   + g * 16 + (sub >> 1) * 8) * 2;
                    uint32_t vhf[4], vlf[4];
                    ldmx4t(vhf, s + 2 * KV_TILE_B + vo);
                    ldmx4t(vlf, s + 3 * KV_TILE_B + vo);
                    mma16816(out[2 * g],     ah, vhf[0], vhf[1]);
                    mma16816(out[2 * g + 1], ah, vhf[2], vhf[3]);
                    mma16816(out[2 * g],     ah, vlf[0], vlf[1]);
                    mma16816(out[2 * g + 1], ah, vlf[2], vlf[3]);
                    mma16816(out[2 * g],     al, vhf[0], vhf[1]);
                    mma16816(out[2 * g + 1], al, vhf[2], vhf[3]);
                }
            }
        }
    }

    // ---- epilogue: normalize, split to bf16 hi/lo, store ctx ----
    l0 += __shfl_xor_sync(0xffffffffu, l0, 1);
    l0 += __shfl_xor_sync(0xffffffffu, l0, 2);
    l1 += __shfl_xor_sync(0xffffffffu, l1, 1);
    l1 += __shfl_xor_sync(0xffffffffu, l1, 2);
    const float inv0 = 1.f / l0, inv1 = 1.f / l1;

#pragma unroll
    for (int g = 0; g < 8; g++) {
        const int d = g * 8 + (lane & 3) * 2;
        const size_t o_lo = ((size_t)b * cS + row_lo) * cD + (size_t)h * cHD + d;
        const size_t o_hi = o_lo + (size_t)8 * cD;
        uint32_t lo32, hi32;
        hi32 = packsplit(out[g][0] * inv0, out[g][1] * inv0, lo32);
        *(uint32_t*)(ch_g + o_lo) = hi32;
        *(uint32_t*)(cl_g + o_lo) = lo32;
        hi32 = packsplit(out[g][2] * inv1, out[g][3] * inv1, lo32);
        *(uint32_t*)(ch_g + o_hi) = hi32;
        *(uint32_t*)(cl_g + o_hi) = lo32;
    }
}

// ---------------------------------------------------------------------------
// Launch
// ---------------------------------------------------------------------------
extern "C" void kernel_launch(void* const* d_in, const int* /*in_sizes*/, int /*n_in*/,
                              void* d_out, int /*out_size*/)
{
    const float* x  = (const float*)d_in[0];
    const float* Wq = (const float*)d_in[1];
    const float* Wk = (const float*)d_in[2];
    const float* Wv = (const float*)d_in[3];
    const float* Wo = (const float*)d_in[4];
    const float* bo = (const float*)d_in[5];
    float* out = (float*)d_out;

    __nv_bfloat16 *xh, *xl, *qh, *ql, *kh, *kl, *vh, *vl, *ch, *cl;
    __nv_bfloat16 *wqh, *wql, *wkh, *wkl, *wvh, *wvl, *woh, *wol;
    cudaGetSymbolAddress((void**)&xh, g_xh);
    cudaGetSymbolAddress((void**)&xl, g_xl);
    cudaGetSymbolAddress((void**)&qh, g_qh);
    cudaGetSymbolAddress((void**)&ql, g_ql);
    cudaGetSymbolAddress((void**)&kh, g_kh);
    cudaGetSymbolAddress((void**)&kl, g_kl);
    cudaGetSymbolAddress((void**)&vh, g_vh);
    cudaGetSymbolAddress((void**)&vl, g_vl);
    cudaGetSymbolAddress((void**)&ch, g_ch);
    cudaGetSymbolAddress((void**)&cl, g_cl);
    cudaGetSymbolAddress((void**)&wqh, g_Wqh);
    cudaGetSymbolAddress((void**)&wql, g_Wql);
    cudaGetSymbolAddress((void**)&wkh, g_Wkh);
    cudaGetSymbolAddress((void**)&wkl, g_Wkl);
    cudaGetSymbolAddress((void**)&wvh, g_Wvh);
    cudaGetSymbolAddress((void**)&wvl, g_Wvl);
    cudaGetSymbolAddress((void**)&woh, g_Woh);
    cudaGetSymbolAddress((void**)&wol, g_Wol);

    cudaFuncSetAttribute(gemm_qkv_kernel,
                         cudaFuncAttributeMaxDynamicSharedMemorySize, GEMM_SMEM);
    cudaFuncSetAttribute(gemm_out_kernel,
                         cudaFuncAttributeMaxDynamicSharedMemorySize, GEMM_SMEM);
    cudaFuncSetAttribute(attn_tc_kernel,
                         cudaFuncAttributeMaxDynamicSharedMemorySize, ATTN_SMEM);

    const int n4 = cM * cD / 4;
    split_kernel<<<(n4 + 255) / 256, 256>>>((const float4*)x, xh, xl, n4);

    dim3 tg(cD / 32, cD / 32, 4), tb(32, 8);
    tsplit4_kernel<<<tg, tb>>>(Wq, Wk, Wv, Wo,
                               wqh, wql, wkh, wkl, wvh, wvl, woh, wol);

    dim3 gq(24, cM / 128);  // (24, 32) — fused QKV
    gemm_qkv_kernel<<<gq, 256, GEMM_SMEM>>>(xh, xl, wqh, wql, wkh, wkl, wvh, wvl,
                                            qh, ql, kh, kl, vh, vl);

    dim3 ga(cS / 128, cH, cB);    // (16, 16, 2)
    attn_tc_kernel<<<ga, 256, ATTN_SMEM>>>(qh, ql, kh, kl, vh, vl, ch, cl);

    dim3 go(cD / 128, cM / 128);  // (8, 32)
    gemm_out_kernel<<<go, 256, GEMM_SMEM>>>(ch, cl, woh, wol, bo, out);
}

// round 15
// speedup vs baseline: 1.0015x; 1.0015x over previous
#include <cuda_runtime.h>
#include <cuda_bf16.h>
#include <cstdint>
#include <math.h>

// Problem constants
constexpr int cB  = 2;
constexpr int cS  = 2048;
constexpr int cD  = 1024;
constexpr int cH  = 16;
constexpr int cHD = 64;
constexpr int cM  = cB * cS;  // 4096 rows

// ---------------------------------------------------------------------------
// Scratch (allocation-free rule: __device__ globals)
// ---------------------------------------------------------------------------
__device__ __nv_bfloat16 g_xh[cM * cD], g_xl[cM * cD];
__device__ __nv_bfloat16 g_qh[cM * cD], g_ql[cM * cD];
__device__ __nv_bfloat16 g_kh[cM * cD], g_kl[cM * cD];
__device__ __nv_bfloat16 g_vh[cM * cD], g_vl[cM * cD];
__device__ __nv_bfloat16 g_ch[cM * cD], g_cl[cM * cD];
__device__ __nv_bfloat16 g_Wqh[cD * cD], g_Wql[cD * cD];
__device__ __nv_bfloat16 g_Wkh[cD * cD], g_Wkl[cD * cD];
__device__ __nv_bfloat16 g_Wvh[cD * cD], g_Wvl[cD * cD];
__device__ __nv_bfloat16 g_Woh[cD * cD], g_Wol[cD * cD];

// Single shared-memory symbol for all dynamic-smem kernels
extern __shared__ char smem_raw[];

// ---------------------------------------------------------------------------
// Helpers (sm_80-era features only: ldmatrix, mma.sync bf16, cp.async)
// ---------------------------------------------------------------------------
__device__ __forceinline__ uint32_t smem_to_u32(const void* smem_ptr) {
    uint32_t addr;
    asm("{ .reg .u64 tmp; cvta.to.shared.u64 tmp, %1; cvt.u32.u64 %0, tmp; }"
        : "=r"(addr) : "l"(smem_ptr));
    return addr;
}

__device__ __forceinline__ void cp_async16(uint32_t dst, const void* src) {
    asm volatile("cp.async.cg.shared.global [%0], [%1], 16;" :: "r"(dst), "l"(src));
}
#define CP_COMMIT() asm volatile("cp.async.commit_group;" ::: "memory")
#define CP_WAIT0()  asm volatile("cp.async.wait_group 0;"  ::: "memory")

__device__ __forceinline__ void ldmx4(uint32_t* d, uint32_t addr) {
    asm volatile("ldmatrix.sync.aligned.m8n8.x4.shared.b16 {%0,%1,%2,%3}, [%4];"
                 : "=r"(d[0]), "=r"(d[1]), "=r"(d[2]), "=r"(d[3]) : "r"(addr));
}
__device__ __forceinline__ void ldmx4t(uint32_t* d, uint32_t addr) {
    asm volatile("ldmatrix.sync.aligned.m8n8.x4.trans.shared.b16 {%0,%1,%2,%3}, [%4];"
                 : "=r"(d[0]), "=r"(d[1]), "=r"(d[2]), "=r"(d[3]) : "r"(addr));
}

__device__ __forceinline__ void mma16816(float* c, const uint32_t* a,
                                         uint32_t b0, uint32_t b1) {
    asm volatile(
        "mma.sync.aligned.m16n8k16.row.col.f32.bf16.bf16.f32 "
        "{%0,%1,%2,%3}, {%4,%5,%6,%7}, {%8,%9}, {%0,%1,%2,%3};"
        : "+f"(c[0]), "+f"(c[1]), "+f"(c[2]), "+f"(c[3])
        : "r"(a[0]), "r"(a[1]), "r"(a[2]), "r"(a[3]), "r"(b0), "r"(b1));
}

__device__ __forceinline__ float exp2a(float x) {
    float y;
    asm("ex2.approx.f32 %0, %1;" : "=f"(y) : "f"(x));
    return y;
}

// pack two fp32 into bf16x2 hi part, return lo residual bf16x2 via out-param
__device__ __forceinline__ uint32_t packsplit(float p0, float p1, uint32_t& lo) {
    __nv_bfloat16 h0 = __float2bfloat16(p0);
    __nv_bfloat16 h1 = __float2bfloat16(p1);
    __nv_bfloat162 hv; hv.x = h0; hv.y = h1;
    __nv_bfloat162 lv;
    lv.x = __float2bfloat16(p0 - __bfloat162float(h0));
    lv.y = __float2bfloat16(p1 - __bfloat162float(h1));
    lo = *(uint32_t*)&lv;
    return *(uint32_t*)&hv;
}

// ---------------------------------------------------------------------------
// bf16-split (Ootomo) mma.sync GEMM core: C = (Ah+Al)[M,K] @ (Bh+Bl)[N,K]^T
// 128x128x32 CTA tile, 256 threads (8 warps, 4x2), warp tile 32x64,
// 2-stage cp.async, __launch_bounds__(256,2) -> 2 CTAs/SM (16 warps/SM).
// ---------------------------------------------------------------------------
constexpr int BKg = 32;
constexpr int LDT = BKg + 8;                    // 40 bf16 per smem row
constexpr int TILE_E  = 128 * LDT;              // 5120 elems
constexpr int STAGE_E = 4 * TILE_E;             // Ah, Al, Bh, Bl
constexpr int GEMM_SMEM = 2 * STAGE_E * 2;      // 81920 bytes
constexpr int NCH = cD / BKg;                   // 32 k-chunks

template <bool SPLIT_OUT>
__device__ __forceinline__ void gemm_core(
    const __nv_bfloat16* __restrict__ Ah, const __nv_bfloat16* __restrict__ Al,
    const __nv_bfloat16* __restrict__ Bh, const __nv_bfloat16* __restrict__ Bl,
    const float* __restrict__ bias, float* __restrict__ C,
    __nv_bfloat16* __restrict__ Ch, __nv_bfloat16* __restrict__ Cl,
    int m0, int n0)
{
    const uint32_t sbase = smem_to_u32(smem_raw);
    const int tid = threadIdx.x, wid = tid >> 5, lane = tid & 31;

    const int r0v = tid >> 2, s0v = tid & 3;          // vector tid
    const int r1v = (tid + 256) >> 2;                 // vector tid+256

    const __nv_bfloat16* gAh = Ah + (size_t)m0 * cD;
    const __nv_bfloat16* gAl = Al + (size_t)m0 * cD;
    const __nv_bfloat16* gBh = Bh + (size_t)n0 * cD;
    const __nv_bfloat16* gBl = Bl + (size_t)n0 * cD;

    auto load_stage = [&](int chunk, int stage) {
        const int k0 = chunk * BKg;
        const uint32_t sb = sbase + (uint32_t)stage * STAGE_E * 2;
        const uint32_t o0 = (uint32_t)(r0v * LDT + s0v * 8) * 2;
        const uint32_t o1 = (uint32_t)(r1v * LDT + s0v * 8) * 2;
        const size_t g0 = (size_t)r0v * cD + k0 + s0v * 8;
        const size_t g1 = (size_t)r1v * cD + k0 + s0v * 8;
        cp_async16(sb + o0,                  gAh + g0);
        cp_async16(sb + o1,                  gAh + g1);
        cp_async16(sb + TILE_E * 2 + o0,     gAl + g0);
        cp_async16(sb + TILE_E * 2 + o1,     gAl + g1);
        cp_async16(sb + 2 * TILE_E * 2 + o0, gBh + g0);
        cp_async16(sb + 2 * TILE_E * 2 + o1, gBh + g1);
        cp_async16(sb + 3 * TILE_E * 2 + o0, gBl + g0);
        cp_async16(sb + 3 * TILE_E * 2 + o1, gBl + g1);
        CP_COMMIT();
    };

    // Warp tiling: 4 (m) x 2 (n) warps; warp tile 32x64
    const int mb = (wid >> 1) * 32;
    const int nb = (wid & 1) * 64;
    const int lr  = lane & 7;
    const int sub = lane >> 3;

    float acc[2][8][4];
#pragma unroll
    for (int i = 0; i < 2; i++)
#pragma unroll
        for (int j = 0; j < 8; j++)
#pragma unroll
            for (int q = 0; q < 4; q++) acc[i][j][q] = 0.f;

    load_stage(0, 0);

    for (int i = 0; i < NCH; i++) {
        CP_WAIT0();
        __syncthreads();
        if (i + 1 < NCH) load_stage(i + 1, (i + 1) & 1);

        const uint32_t sb  = sbase + (uint32_t)(i & 1) * STAGE_E * 2;
        const uint32_t sAh = sb;
        const uint32_t sAl = sb + TILE_E * 2;
        const uint32_t sBh = sb + 2 * TILE_E * 2;
        const uint32_t sBl = sb + 3 * TILE_E * 2;

#pragma unroll
        for (int ks = 0; ks < 2; ks++) {
            const int kc = ks * 16 + (sub >> 1) * 8;
            uint32_t ah[2][4], al[2][4];
#pragma unroll
            for (int mf = 0; mf < 2; mf++) {
                const uint32_t off =
                    (uint32_t)((mb + mf * 16 + (sub & 1) * 8 + lr) * LDT + kc) * 2;
                ldmx4(ah[mf], sAh + off);
                ldmx4(al[mf], sAl + off);
            }
#pragma unroll
            for (int p = 0; p < 4; p++) {
                const uint32_t boff =
                    (uint32_t)((nb + p * 16 + (sub & 1) * 8 + lr) * LDT + kc) * 2;
                uint32_t bh[4], bl[4];
                ldmx4(bh, sBh + boff);
                ldmx4(bl, sBl + boff);
#pragma unroll
                for (int mf = 0; mf < 2; mf++) {
                    mma16816(acc[mf][2 * p],     ah[mf], bh[0], bh[2]);
                    mma16816(acc[mf][2 * p + 1], ah[mf], bh[1], bh[3]);
                    mma16816(acc[mf][2 * p],     ah[mf], bl[0], bl[2]);
                    mma16816(acc[mf][2 * p + 1], ah[mf], bl[1], bl[3]);
                    mma16816(acc[mf][2 * p],     al[mf], bh[0], bh[2]);
                    mma16816(acc[mf][2 * p + 1], al[mf], bh[1], bh[3]);
                }
            }
        }
        __syncthreads();
    }

    // Epilogue
    const int er = lane >> 2;
    const int ec = (lane & 3) * 2;
    if (SPLIT_OUT) {
#pragma unroll
        for (int mf = 0; mf < 2; mf++) {
#pragma unroll
            for (int nf = 0; nf < 8; nf++) {
                const int row = m0 + mb + mf * 16 + er;
                const int col = n0 + nb + nf * 8 + ec;
                uint32_t lo, hi;
                hi = packsplit(acc[mf][nf][0], acc[mf][nf][1], lo);
                *(uint32_t*)(Ch + (size_t)row * cD + col) = hi;
                *(uint32_t*)(Cl + (size_t)row * cD + col) = lo;
                hi = packsplit(acc[mf][nf][2], acc[mf][nf][3], lo);
                *(uint32_t*)(Ch + (size_t)(row + 8) * cD + col) = hi;
                *(uint32_t*)(Cl + (size_t)(row + 8) * cD + col) = lo;
            }
        }
    } else {
#pragma unroll
        for (int mf = 0; mf < 2; mf++) {
#pragma unroll
            for (int nf = 0; nf < 8; nf++) {
                const int row = m0 + mb + mf * 16 + er;
                const int col = n0 + nb + nf * 8 + ec;
                const float b0 = bias[col], b1 = bias[col + 1];
                float2 v0 = make_float2(acc[mf][nf][0] + b0, acc[mf][nf][1] + b1);
                float2 v1 = make_float2(acc[mf][nf][2] + b0, acc[mf][nf][3] + b1);
                *(float2*)(C + (size_t)row * cD + col)       = v0;
                *(float2*)(C + (size_t)(row + 8) * cD + col) = v1;
            }
        }
    }
}

// Fused QKV projection: grid (24, 32); blockIdx.x>>3 selects {Wq,Wk,Wv}
__global__ void __launch_bounds__(256, 2) gemm_qkv_kernel(
    const __nv_bfloat16* __restrict__ xh, const __nv_bfloat16* __restrict__ xl,
    const __nv_bfloat16* __restrict__ wqh, const __nv_bfloat16* __restrict__ wql,
    const __nv_bfloat16* __restrict__ wkh, const __nv_bfloat16* __restrict__ wkl,
    const __nv_bfloat16* __restrict__ wvh, const __nv_bfloat16* __restrict__ wvl,
    __nv_bfloat16* __restrict__ qh, __nv_bfloat16* __restrict__ ql,
    __nv_bfloat16* __restrict__ kh, __nv_bfloat16* __restrict__ kl,
    __nv_bfloat16* __restrict__ vh, __nv_bfloat16* __restrict__ vl)
{
    const int sel = blockIdx.x >> 3;
    const int n0 = (blockIdx.x & 7) * 128;
    const int m0 = blockIdx.y * 128;
    const __nv_bfloat16 *Bh, *Bl;
    __nv_bfloat16 *Oh, *Ol;
    if (sel == 0)      { Bh = wqh; Bl = wql; Oh = qh; Ol = ql; }
    else if (sel == 1) { Bh = wkh; Bl = wkl; Oh = kh; Ol = kl; }
    else               { Bh = wvh; Bl = wvl; Oh = vh; Ol = vl; }
    gemm_core<true>(xh, xl, Bh, Bl, nullptr, nullptr, Oh, Ol, m0, n0);
}

// Output projection: fp32 + bias
__global__ void __launch_bounds__(256, 2) gemm_out_kernel(
    const __nv_bfloat16* __restrict__ ch, const __nv_bfloat16* __restrict__ cl,
    const __nv_bfloat16* __restrict__ woh, const __nv_bfloat16* __restrict__ wol,
    const float* __restrict__ bias, float* __restrict__ out)
{
    gemm_core<false>(ch, cl, woh, wol, bias, out, nullptr, nullptr,
                     blockIdx.y * 128, blockIdx.x * 128);
}

// ---------------------------------------------------------------------------
// fp32 -> bf16 hi/lo split (elementwise, vectorized)
// ---------------------------------------------------------------------------
__global__ void __launch_bounds__(256) split_kernel(
    const float4* __restrict__ a, __nv_bfloat16* __restrict__ hi,
    __nv_bfloat16* __restrict__ lo, int n4)
{
    int i = blockIdx.x * blockDim.x + threadIdx.x;
    if (i >= n4) return;
    float4 v = a[i];
    uint32_t l01, l23;
    uint32_t h01 = packsplit(v.x, v.y, l01);
    uint32_t h23 = packsplit(v.z, v.w, l23);
    ((uint32_t*)hi)[i * 2]     = h01;
    ((uint32_t*)hi)[i * 2 + 1] = h23;
    ((uint32_t*)lo)[i * 2]     = l01;
    ((uint32_t*)lo)[i * 2 + 1] = l23;
}

// ---------------------------------------------------------------------------
// Fused weight transpose + split for all 4 weights (blockIdx.z selects W)
// ---------------------------------------------------------------------------
__global__ void __launch_bounds__(256) tsplit4_kernel(
    const float* __restrict__ Wq, const float* __restrict__ Wk,
    const float* __restrict__ Wv, const float* __restrict__ Wo,
    __nv_bfloat16* __restrict__ qh, __nv_bfloat16* __restrict__ ql,
    __nv_bfloat16* __restrict__ kh, __nv_bfloat16* __restrict__ kl,
    __nv_bfloat16* __restrict__ vh, __nv_bfloat16* __restrict__ vl,
    __nv_bfloat16* __restrict__ oh, __nv_bfloat16* __restrict__ ol)
{
    __shared__ float s[32][33];
    const float* W;
    __nv_bfloat16 *Th, *Tl;
    switch (blockIdx.z) {
        case 0:  W = Wq; Th = qh; Tl = ql; break;
        case 1:  W = Wk; Th = kh; Tl = kl; break;
        case 2:  W = Wv; Th = vh; Tl = vl; break;
        default: W = Wo; Th = oh; Tl = ol; break;
    }
    const int n0 = blockIdx.x * 32;
    const int k0 = blockIdx.y * 32;
    const int tx = threadIdx.x, ty = threadIdx.y;  // 32 x 8
#pragma unroll
    for (int r = 0; r < 32; r += 8)
        s[ty + r][tx] = W[(size_t)(k0 + ty + r) * cD + n0 + tx];
    __syncthreads();
#pragma unroll
    for (int r = 0; r < 32; r += 8) {
        float v = s[tx][ty + r];
        __nv_bfloat16 h = __float2bfloat16(v);
        __nv_bfloat16 l = __float2bfloat16(v - __bfloat162float(h));
        size_t o = (size_t)(n0 + ty + r) * cD + k0 + tx;
        Th[o] = h; Tl[o] = l;
    }
}

// ---------------------------------------------------------------------------
// Tensor-core causal flash attention (bf16 split, fp32 accum).
// __launch_bounds__(256, 2) -> 2 CTAs/SM (16 warps/SM).
// ---------------------------------------------------------------------------
constexpr int ALD = 72;                       // padded row length (bf16 elems)
constexpr int KV_TILE_B = 64 * ALD * 2;       // 9216 bytes
constexpr int KV_STB = 4 * KV_TILE_B;         // stage: Kh,Kl,Vh,Vl = 36864
constexpr int ATTN_SMEM = 2 * KV_STB;         // 73728
constexpr float CQ = 0.18033688011112042f;    // 0.125 * log2(e)

__global__ void __launch_bounds__(256, 2) attn_tc_kernel(
    const __nv_bfloat16* __restrict__ qh_g, const __nv_bfloat16* __restrict__ ql_g,
    const __nv_bfloat16* __restrict__ kh_g, const __nv_bfloat16* __restrict__ kl_g,
    const __nv_bfloat16* __restrict__ vh_g, const __nv_bfloat16* __restrict__ vl_g,
    __nv_bfloat16* __restrict__ ch_g, __nv_bfloat16* __restrict__ cl_g)
{
    const uint32_t sb0 = smem_to_u32(smem_raw);

    const int tid = threadIdx.x, wid = tid >> 5, lane = tid & 31;
    const int qt = (int)gridDim.x - 1 - (int)blockIdx.x;  // big tiles first
    const int h = blockIdx.y, b = blockIdx.z;
    const int qbase = qt * 128 + wid * 16;
    const size_t gb = (size_t)b * cS * cD + (size_t)h * cHD;

    const int vrow = tid >> 3, vseg = tid & 7;
    auto load_kv = [&](int t, int stage) {
        const int k0 = t * 64;
        const uint32_t s = sb0 + stage * KV_STB;
#pragma unroll
        for (int r = 0; r < 2; r++) {
            const int row = vrow + r * 32;
            const size_t g = gb + (size_t)(k0 + row) * cD + vseg * 8;
            const uint32_t so = (uint32_t)(row * ALD + vseg * 8) * 2;
            cp_async16(s + so,                kh_g + g);
            cp_async16(s + KV_TILE_B + so,    kl_g + g);
            cp_async16(s + 2 * KV_TILE_B + so, vh_g + g);
            cp_async16(s + 3 * KV_TILE_B + so, vl_g + g);
        }
    };
    load_kv(0, 0);
    CP_COMMIT();

    // Stage Q tile (hi/lo) into stage-1 region, extract fragments, then the
    // region is recycled for K/V stage 1 (guarded by the t=0 loop sync).
    {
        char* qp = smem_raw + KV_STB;
#pragma unroll
        for (int r = 0; r < 4; r++) {
            const int v = tid + r * 256;          // 0..1023
            const int row = v >> 3, seg = v & 7;
            const size_t g = gb + (size_t)(qt * 128 + row) * cD + seg * 8;
            const uint32_t so = (uint32_t)(row * ALD + seg * 8) * 2;
            *(uint4*)(qp + so)          = *(const uint4*)(qh_g + g);
            *(uint4*)(qp + 18432 + so)  = *(const uint4*)(ql_g + g);
        }
    }
    __syncthreads();
    uint32_t qfh[4][4], qfl[4][4];
    {
        const uint32_t qs = sb0 + KV_STB;
        const int rr = wid * 16 + (lane & 15);
        const int cc = (lane >> 4) * 8;
#pragma unroll
        for (int ks = 0; ks < 4; ks++) {
            const uint32_t off = (uint32_t)(rr * ALD + ks * 16 + cc) * 2;
            ldmx4(qfh[ks], qs + off);
            ldmx4(qfl[ks], qs + 18432 + off);
        }
    }

    float m0 = -1e30f, m1 = -1e30f, l0 = 0.f, l1 = 0.f;
    float out[8][4];
#pragma unroll
    for (int j = 0; j < 8; j++)
#pragma unroll
        for (int q = 0; q < 4; q++) out[j][q] = 0.f;

    const int ntiles = 2 * qt + 2;
    const int sub = lane >> 3, lr = lane & 7;
    const int row_lo = qbase + (lane >> 2);
    const int row_hi = row_lo + 8;

    for (int t = 0; t < ntiles; t++) {
        CP_WAIT0();
        __syncthreads();
        if (t + 1 < ntiles) { load_kv(t + 1, (t + 1) & 1); CP_COMMIT(); }

        const int k0 = t * 64;
        if (k0 <= qbase + 15) {          // any visible keys for this warp
            const uint32_t s = sb0 + (t & 1) * KV_STB;

            // ---- scores: S = Q @ K^T (3-term split) ----
            float sc[8][4];
#pragma unroll
            for (int j = 0; j < 8; j++) {
                sc[j][0] = 0.f; sc[j][1] = 0.f; sc[j][2] = 0.f; sc[j][3] = 0.f;
            }
#pragma unroll
            for (int ks = 0; ks < 4; ks++) {
#pragma unroll
                for (int g = 0; g < 4; g++) {
                    const uint32_t ko = (uint32_t)((g * 16 + (sub & 1) * 8 + lr) * ALD
                                                   + ks * 16 + (sub >> 1) * 8) * 2;
                    uint32_t bh[4], bl[4];
                    ldmx4(bh, s + ko);
                    ldmx4(bl, s + KV_TILE_B + ko);
                    mma16816(sc[2 * g],     qfh[ks], bh[0], bh[2]);
                    mma16816(sc[2 * g + 1], qfh[ks], bh[1], bh[3]);
                    mma16816(sc[2 * g],     qfh[ks], bl[0], bl[2]);
                    mma16816(sc[2 * g + 1], qfh[ks], bl[1], bl[3]);
                    mma16816(sc[2 * g],     qfl[ks], bh[0], bh[2]);
                    mma16816(sc[2 * g + 1], qfl[ks], bh[1], bh[3]);
                }
            }

            // ---- causal mask (diagonal tiles only) ----
            if (k0 + 63 > qbase) {
#pragma unroll
                for (int j = 0; j < 8; j++) {
                    const int c0 = k0 + j * 8 + (lane & 3) * 2;
                    if (c0     > row_lo) sc[j][0] = -1e30f;
                    if (c0 + 1 > row_lo) sc[j][1] = -1e30f;
                    if (c0     > row_hi) sc[j][2] = -1e30f;
                    if (c0 + 1 > row_hi) sc[j][3] = -1e30f;
                }
            }

            // ---- online softmax (raw-score domain, exp2 with CQ) ----
            float mx0 = -1e30f, mx1 = -1e30f;
#pragma unroll
            for (int j = 0; j < 8; j++) {
                mx0 = fmaxf(mx0, fmaxf(sc[j][0], sc[j][1]));
                mx1 = fmaxf(mx1, fmaxf(sc[j][2], sc[j][3]));
            }
            mx0 = fmaxf(mx0, __shfl_xor_sync(0xffffffffu, mx0, 1));
            mx0 = fmaxf(mx0, __shfl_xor_sync(0xffffffffu, mx0, 2));
            mx1 = fmaxf(mx1, __shfl_xor_sync(0xffffffffu, mx1, 1));
            mx1 = fmaxf(mx1, __shfl_xor_sync(0xffffffffu, mx1, 2));
            const float nm0 = fmaxf(m0, mx0), nm1 = fmaxf(m1, mx1);
            const float cr0 = exp2a((m0 - nm0) * CQ);
            const float cr1 = exp2a((m1 - nm1) * CQ);
            m0 = nm0; m1 = nm1;
            l0 *= cr0; l1 *= cr1;
#pragma unroll
            for (int j = 0; j < 8; j++) {
                out[j][0] *= cr0; out[j][1] *= cr0;
                out[j][2] *= cr1; out[j][3] *= cr1;
            }
#pragma unroll
            for (int j = 0; j < 8; j++) {
                sc[j][0] = exp2a((sc[j][0] - m0) * CQ);
                sc[j][1] = exp2a((sc[j][1] - m0) * CQ);
                sc[j][2] = exp2a((sc[j][2] - m1) * CQ);
                sc[j][3] = exp2a((sc[j][3] - m1) * CQ);
                l0 += sc[j][0] + sc[j][1];
                l1 += sc[j][2] + sc[j][3];
            }

            // ---- out += P @ V (3-term split, P split in registers) ----
#pragma unroll
            for (int t2 = 0; t2 < 4; t2++) {
                uint32_t ah[4], al[4];
                ah[0] = packsplit(sc[2 * t2][0],     sc[2 * t2][1],     al[0]);
                ah[1] = packsplit(sc[2 * t2][2],     sc[2 * t2][3],     al[1]);
                ah[2] = packsplit(sc[2 * t2 + 1][0], sc[2 * t2 + 1][1], al[2]);
                ah[3] = packsplit(sc[2 * t2 + 1][2], sc[2 * t2 + 1][3], al[3]);
#pragma unroll
                for (int g = 0; g < 4; g++) {
                    const uint32_t vo = (uint32_t)((t2 * 16 + (sub & 1) * 8 + lr) * ALD
                                                   + g * 16 + (sub >> 1) * 8) * 2;
                    uint32_t vhf[4], vlf[4];
                    ldmx4t(vhf, s + 2 * KV_TILE_B + vo);
                    ldmx4t(vlf, s + 3 * KV_TILE_B + vo);
                    mma16816(out[2 * g],     ah, vhf[0], vhf[1]);
                    mma16816(out[2 * g + 1], ah, vhf[2], vhf[3]);
                    mma16816(out[2 * g],     ah, vlf[0], vlf[1]);
                    mma16816(out[2 * g + 1], ah, vlf[2], vlf[3]);
                    mma16816(out[2 * g],     al, vhf[0], vhf[1]);
                    mma16816(out[2 * g + 1], al, vhf[2], vhf[3]);
                }
            }
        }
    }

    // ---- epilogue: normalize, split to bf16 hi/lo, store ctx ----
    l0 += __shfl_xor_sync(0xffffffffu, l0, 1);
    l0 += __shfl_xor_sync(0xffffffffu, l0, 2);
    l1 += __shfl_xor_sync(0xffffffffu, l1, 1);
    l1 += __shfl_xor_sync(0xffffffffu, l1, 2);
    const float inv0 = 1.f / l0, inv1 = 1.f / l1;

#pragma unroll
    for (int g = 0; g < 8; g++) {
        const int d = g * 8 + (lane & 3) * 2;
        const size_t o_lo = ((size_t)b * cS + row_lo) * cD + (size_t)h * cHD + d;
        const size_t o_hi = o_lo + (size_t)8 * cD;
        uint32_t lo32, hi32;
        hi32 = packsplit(out[g][0] * inv0, out[g][1] * inv0, lo32);
        *(uint32_t*)(ch_g + o_lo) = hi32;
        *(uint32_t*)(cl_g + o_lo) = lo32;
        hi32 = packsplit(out[g][2] * inv1, out[g][3] * inv1, lo32);
        *(uint32_t*)(ch_g + o_hi) = hi32;
        *(uint32_t*)(cl_g + o_hi) = lo32;
    }
}

// ---------------------------------------------------------------------------
// Launch
// ---------------------------------------------------------------------------
extern "C" void kernel_launch(void* const* d_in, const int* /*in_sizes*/, int /*n_in*/,
                              void* d_out, int /*out_size*/)
{
    const float* x  = (const float*)d_in[0];
    const float* Wq = (const float*)d_in[1];
    const float* Wk = (const float*)d_in[2];
    const float* Wv = (const float*)d_in[3];
    const float* Wo = (const float*)d_in[4];
    const float* bo = (const float*)d_in[5];
    float* out = (float*)d_out;

    __nv_bfloat16 *xh, *xl, *qh, *ql, *kh, *kl, *vh, *vl, *ch, *cl;
    __nv_bfloat16 *wqh, *wql, *wkh, *wkl, *wvh, *wvl, *woh, *wol;
    cudaGetSymbolAddress((void**)&xh, g_xh);
    cudaGetSymbolAddress((void**)&xl, g_xl);
    cudaGetSymbolAddress((void**)&qh, g_qh);
    cudaGetSymbolAddress((void**)&ql, g_ql);
    cudaGetSymbolAddress((void**)&kh, g_kh);
    cudaGetSymbolAddress((void**)&kl, g_kl);
    cudaGetSymbolAddress((void**)&vh, g_vh);
    cudaGetSymbolAddress((void**)&vl, g_vl);
    cudaGetSymbolAddress((void**)&ch, g_ch);
    cudaGetSymbolAddress((void**)&cl, g_cl);
    cudaGetSymbolAddress((void**)&wqh, g_Wqh);
    cudaGetSymbolAddress((void**)&wql, g_Wql);
    cudaGetSymbolAddress((void**)&wkh, g_Wkh);
    cudaGetSymbolAddress((void**)&wkl, g_Wkl);
    cudaGetSymbolAddress((void**)&wvh, g_Wvh);
    cudaGetSymbolAddress((void**)&wvl, g_Wvl);
    cudaGetSymbolAddress((void**)&woh, g_Woh);
    cudaGetSymbolAddress((void**)&wol, g_Wol);

    cudaFuncSetAttribute(gemm_qkv_kernel,
                         cudaFuncAttributeMaxDynamicSharedMemorySize, GEMM_SMEM);
    cudaFuncSetAttribute(gemm_out_kernel,
                         cudaFuncAttributeMaxDynamicSharedMemorySize, GEMM_SMEM);
    cudaFuncSetAttribute(attn_tc_kernel,
                         cudaFuncAttributeMaxDynamicSharedMemorySize, ATTN_SMEM);

    const int n4 = cM * cD / 4;
    split_kernel<<<(n4 + 255) / 256, 256>>>((const float4*)x, xh, xl, n4);

    dim3 tg(cD / 32, cD / 32, 4), tb(32, 8);
    tsplit4_kernel<<<tg, tb>>>(Wq, Wk, Wv, Wo,
                               wqh, wql, wkh, wkl, wvh, wvl, woh, wol);

    dim3 gq(24, cM / 128);  // (24, 32) — fused QKV
    gemm_qkv_kernel<<<gq, 256, GEMM_SMEM>>>(xh, xl, wqh, wql, wkh, wkl, wvh, wvl,
                                            qh, ql, kh, kl, vh, vl);

    dim3 ga(cS / 128, cH, cB);    // (16, 16, 2)
    attn_tc_kernel<<<ga, 256, ATTN_SMEM>>>(qh, ql, kh, kl, vh, vl, ch, cl);

    dim3 go(cD / 128, cM / 128);  // (8, 32)
    gemm_out_kernel<<<go, 256, GEMM_SMEM>>>(ch, cl, woh, wol, bo, out);
}

// round 16
// speedup vs baseline: 1.0107x; 1.0092x over previous
#include <cuda_runtime.h>
#include <cuda_bf16.h>
#include <cstdint>
#include <math.h>

// Problem constants
constexpr int cB  = 2;
constexpr int cS  = 2048;
constexpr int cD  = 1024;
constexpr int cH  = 16;
constexpr int cHD = 64;
constexpr int cM  = cB * cS;  // 4096 rows

// ---------------------------------------------------------------------------
// Scratch (allocation-free rule: __device__ globals)
// ---------------------------------------------------------------------------
__device__ __nv_bfloat16 g_xh[cM * cD], g_xl[cM * cD];
__device__ __nv_bfloat16 g_qh[cM * cD], g_ql[cM * cD];
__device__ __nv_bfloat16 g_kh[cM * cD], g_kl[cM * cD];
__device__ __nv_bfloat16 g_vh[cM * cD], g_vl[cM * cD];
__device__ __nv_bfloat16 g_ch[cM * cD], g_cl[cM * cD];
__device__ __nv_bfloat16 g_Wqh[cD * cD], g_Wql[cD * cD];
__device__ __nv_bfloat16 g_Wkh[cD * cD], g_Wkl[cD * cD];
__device__ __nv_bfloat16 g_Wvh[cD * cD], g_Wvl[cD * cD];
__device__ __nv_bfloat16 g_Woh[cD * cD], g_Wol[cD * cD];

// Single shared-memory symbol for all dynamic-smem kernels
extern __shared__ char smem_raw[];

// ---------------------------------------------------------------------------
// Helpers (sm_80-era features only: ldmatrix, mma.sync bf16, cp.async)
// ---------------------------------------------------------------------------
__device__ __forceinline__ uint32_t smem_to_u32(const void* smem_ptr) {
    uint32_t addr;
    asm("{ .reg .u64 tmp; cvta.to.shared.u64 tmp, %1; cvt.u32.u64 %0, tmp; }"
        : "=r"(addr) : "l"(smem_ptr));
    return addr;
}

__device__ __forceinline__ void cp_async16(uint32_t dst, const void* src) {
    asm volatile("cp.async.cg.shared.global [%0], [%1], 16;" :: "r"(dst), "l"(src));
}
#define CP_COMMIT() asm volatile("cp.async.commit_group;" ::: "memory")
#define CP_WAIT0()  asm volatile("cp.async.wait_group 0;"  ::: "memory")

__device__ __forceinline__ void ldmx4(uint32_t* d, uint32_t addr) {
    asm volatile("ldmatrix.sync.aligned.m8n8.x4.shared.b16 {%0,%1,%2,%3}, [%4];"
                 : "=r"(d[0]), "=r"(d[1]), "=r"(d[2]), "=r"(d[3]) : "r"(addr));
}
__device__ __forceinline__ void ldmx4t(uint32_t* d, uint32_t addr) {
    asm volatile("ldmatrix.sync.aligned.m8n8.x4.trans.shared.b16 {%0,%1,%2,%3}, [%4];"
                 : "=r"(d[0]), "=r"(d[1]), "=r"(d[2]), "=r"(d[3]) : "r"(addr));
}

__device__ __forceinline__ void mma16816(float* c, const uint32_t* a,
                                         uint32_t b0, uint32_t b1) {
    asm volatile(
        "mma.sync.aligned.m16n8k16.row.col.f32.bf16.bf16.f32 "
        "{%0,%1,%2,%3}, {%4,%5,%6,%7}, {%8,%9}, {%0,%1,%2,%3};"
        : "+f"(c[0]), "+f"(c[1]), "+f"(c[2]), "+f"(c[3])
        : "r"(a[0]), "r"(a[1]), "r"(a[2]), "r"(a[3]), "r"(b0), "r"(b1));
}

__device__ __forceinline__ float exp2a(float x) {
    float y;
    asm("ex2.approx.f32 %0, %1;" : "=f"(y) : "f"(x));
    return y;
}

// pack two fp32 into bf16x2 hi part, return lo residual bf16x2 via out-param
__device__ __forceinline__ uint32_t packsplit(float p0, float p1, uint32_t& lo) {
    __nv_bfloat16 h0 = __float2bfloat16(p0);
    __nv_bfloat16 h1 = __float2bfloat16(p1);
    __nv_bfloat162 hv; hv.x = h0; hv.y = h1;
    __nv_bfloat162 lv;
    lv.x = __float2bfloat16(p0 - __bfloat162float(h0));
    lv.y = __float2bfloat16(p1 - __bfloat162float(h1));
    lo = *(uint32_t*)&lv;
    return *(uint32_t*)&hv;
}

// ---------------------------------------------------------------------------
// bf16-split (Ootomo) mma.sync GEMM core: C = (Ah+Al)[M,K] @ (Bh+Bl)[N,K]^T
// 128x128x32 CTA tile, 256 threads (8 warps, 4x2), warp tile 32x64,
// 2-stage cp.async, __launch_bounds__(256,2) -> 2 CTAs/SM (16 warps/SM).
// ---------------------------------------------------------------------------
constexpr int BKg = 32;
constexpr int LDT = BKg + 8;                    // 40 bf16 per smem row
constexpr int TILE_E  = 128 * LDT;              // 5120 elems
constexpr int STAGE_E = 4 * TILE_E;             // Ah, Al, Bh, Bl
constexpr int GEMM_SMEM = 2 * STAGE_E * 2;      // 81920 bytes
constexpr int NCH = cD / BKg;                   // 32 k-chunks

template <bool SPLIT_OUT>
__device__ __forceinline__ void gemm_core(
    const __nv_bfloat16* __restrict__ Ah, const __nv_bfloat16* __restrict__ Al,
    const __nv_bfloat16* __restrict__ Bh, const __nv_bfloat16* __restrict__ Bl,
    const float* __restrict__ bias, float* __restrict__ C,
    __nv_bfloat16* __restrict__ Ch, __nv_bfloat16* __restrict__ Cl,
    int m0, int n0)
{
    const uint32_t sbase = smem_to_u32(smem_raw);
    const int tid = threadIdx.x, wid = tid >> 5, lane = tid & 31;

    const int r0v = tid >> 2, s0v = tid & 3;          // vector tid
    const int r1v = (tid + 256) >> 2;                 // vector tid+256

    const __nv_bfloat16* gAh = Ah + (size_t)m0 * cD;
    const __nv_bfloat16* gAl = Al + (size_t)m0 * cD;
    const __nv_bfloat16* gBh = Bh + (size_t)n0 * cD;
    const __nv_bfloat16* gBl = Bl + (size_t)n0 * cD;

    auto load_stage = [&](int chunk, int stage) {
        const int k0 = chunk * BKg;
        const uint32_t sb = sbase + (uint32_t)stage * STAGE_E * 2;
        const uint32_t o0 = (uint32_t)(r0v * LDT + s0v * 8) * 2;
        const uint32_t o1 = (uint32_t)(r1v * LDT + s0v * 8) * 2;
        const size_t g0 = (size_t)r0v * cD + k0 + s0v * 8;
        const size_t g1 = (size_t)r1v * cD + k0 + s0v * 8;
        cp_async16(sb + o0,                  gAh + g0);
        cp_async16(sb + o1,                  gAh + g1);
        cp_async16(sb + TILE_E * 2 + o0,     gAl + g0);
        cp_async16(sb + TILE_E * 2 + o1,     gAl + g1);
        cp_async16(sb + 2 * TILE_E * 2 + o0, gBh + g0);
        cp_async16(sb + 2 * TILE_E * 2 + o1, gBh + g1);
        cp_async16(sb + 3 * TILE_E * 2 + o0, gBl + g0);
        cp_async16(sb + 3 * TILE_E * 2 + o1, gBl + g1);
        CP_COMMIT();
    };

    // Warp tiling: 4 (m) x 2 (n) warps; warp tile 32x64
    const int mb = (wid >> 1) * 32;
    const int nb = (wid & 1) * 64;
    const int lr  = lane & 7;
    const int sub = lane >> 3;

    float acc[2][8][4];
#pragma unroll
    for (int i = 0; i < 2; i++)
#pragma unroll
        for (int j = 0; j < 8; j++)
#pragma unroll
            for (int q = 0; q < 4; q++) acc[i][j][q] = 0.f;

    load_stage(0, 0);

    for (int i = 0; i < NCH; i++) {
        CP_WAIT0();
        __syncthreads();
        if (i + 1 < NCH) load_stage(i + 1, (i + 1) & 1);

        const uint32_t sb  = sbase + (uint32_t)(i & 1) * STAGE_E * 2;
        const uint32_t sAh = sb;
        const uint32_t sAl = sb + TILE_E * 2;
        const uint32_t sBh = sb + 2 * TILE_E * 2;
        const uint32_t sBl = sb + 3 * TILE_E * 2;

#pragma unroll
        for (int ks = 0; ks < 2; ks++) {
            const int kc = ks * 16 + (sub >> 1) * 8;
            uint32_t ah[2][4], al[2][4];
#pragma unroll
            for (int mf = 0; mf < 2; mf++) {
                const uint32_t off =
                    (uint32_t)((mb + mf * 16 + (sub & 1) * 8 + lr) * LDT + kc) * 2;
                ldmx4(ah[mf], sAh + off);
                ldmx4(al[mf], sAl + off);
            }
#pragma unroll
            for (int p = 0; p < 4; p++) {
                const uint32_t boff =
                    (uint32_t)((nb + p * 16 + (sub & 1) * 8 + lr) * LDT + kc) * 2;
                uint32_t bh[4], bl[4];
                ldmx4(bh, sBh + boff);
                ldmx4(bl, sBl + boff);
#pragma unroll
                for (int mf = 0; mf < 2; mf++) {
                    mma16816(acc[mf][2 * p],     ah[mf], bh[0], bh[2]);
                    mma16816(acc[mf][2 * p + 1], ah[mf], bh[1], bh[3]);
                    mma16816(acc[mf][2 * p],     ah[mf], bl[0], bl[2]);
                    mma16816(acc[mf][2 * p + 1], ah[mf], bl[1], bl[3]);
                    mma16816(acc[mf][2 * p],     al[mf], bh[0], bh[2]);
                    mma16816(acc[mf][2 * p + 1], al[mf], bh[1], bh[3]);
                }
            }
        }
        __syncthreads();
    }

    // Epilogue
    const int er = lane >> 2;
    const int ec = (lane & 3) * 2;
    if (SPLIT_OUT) {
#pragma unroll
        for (int mf = 0; mf < 2; mf++) {
#pragma unroll
            for (int nf = 0; nf < 8; nf++) {
                const int row = m0 + mb + mf * 16 + er;
                const int col = n0 + nb + nf * 8 + ec;
                uint32_t lo, hi;
                hi = packsplit(acc[mf][nf][0], acc[mf][nf][1], lo);
                *(uint32_t*)(Ch + (size_t)row * cD + col) = hi;
                *(uint32_t*)(Cl + (size_t)row * cD + col) = lo;
                hi = packsplit(acc[mf][nf][2], acc[mf][nf][3], lo);
                *(uint32_t*)(Ch + (size_t)(row + 8) * cD + col) = hi;
                *(uint32_t*)(Cl + (size_t)(row + 8) * cD + col) = lo;
            }
        }
    } else {
#pragma unroll
        for (int mf = 0; mf < 2; mf++) {
#pragma unroll
            for (int nf = 0; nf < 8; nf++) {
                const int row = m0 + mb + mf * 16 + er;
                const int col = n0 + nb + nf * 8 + ec;
                const float b0 = bias[col], b1 = bias[col + 1];
                float2 v0 = make_float2(acc[mf][nf][0] + b0, acc[mf][nf][1] + b1);
                float2 v1 = make_float2(acc[mf][nf][2] + b0, acc[mf][nf][3] + b1);
                *(float2*)(C + (size_t)row * cD + col)       = v0;
                *(float2*)(C + (size_t)(row + 8) * cD + col) = v1;
            }
        }
    }
}

// Fused QKV projection: grid (24, 32); blockIdx.x>>3 selects {Wq,Wk,Wv}
__global__ void __launch_bounds__(256, 2) gemm_qkv_kernel(
    const __nv_bfloat16* __restrict__ xh, const __nv_bfloat16* __restrict__ xl,
    const __nv_bfloat16* __restrict__ wqh, const __nv_bfloat16* __restrict__ wql,
    const __nv_bfloat16* __restrict__ wkh, const __nv_bfloat16* __restrict__ wkl,
    const __nv_bfloat16* __restrict__ wvh, const __nv_bfloat16* __restrict__ wvl,
    __nv_bfloat16* __restrict__ qh, __nv_bfloat16* __restrict__ ql,
    __nv_bfloat16* __restrict__ kh, __nv_bfloat16* __restrict__ kl,
    __nv_bfloat16* __restrict__ vh, __nv_bfloat16* __restrict__ vl)
{
    const int sel = blockIdx.x >> 3;
    const int n0 = (blockIdx.x & 7) * 128;
    const int m0 = blockIdx.y * 128;
    const __nv_bfloat16 *Bh, *Bl;
    __nv_bfloat16 *Oh, *Ol;
    if (sel == 0)      { Bh = wqh; Bl = wql; Oh = qh; Ol = ql; }
    else if (sel == 1) { Bh = wkh; Bl = wkl; Oh = kh; Ol = kl; }
    else               { Bh = wvh; Bl = wvl; Oh = vh; Ol = vl; }
    gemm_core<true>(xh, xl, Bh, Bl, nullptr, nullptr, Oh, Ol, m0, n0);
}

// Output projection: fp32 + bias
__global__ void __launch_bounds__(256, 2) gemm_out_kernel(
    const __nv_bfloat16* __restrict__ ch, const __nv_bfloat16* __restrict__ cl,
    const __nv_bfloat16* __restrict__ woh, const __nv_bfloat16* __restrict__ wol,
    const float* __restrict__ bias, float* __restrict__ out)
{
    gemm_core<false>(ch, cl, woh, wol, bias, out, nullptr, nullptr,
                     blockIdx.y * 128, blockIdx.x * 128);
}

// ---------------------------------------------------------------------------
// fp32 -> bf16 hi/lo split (elementwise, vectorized)
// ---------------------------------------------------------------------------
__global__ void __launch_bounds__(256) split_kernel(
    const float4* __restrict__ a, __nv_bfloat16* __restrict__ hi,
    __nv_bfloat16* __restrict__ lo, int n4)
{
    int i = blockIdx.x * blockDim.x + threadIdx.x;
    if (i >= n4) return;
    float4 v = a[i];
    uint32_t l01, l23;
    uint32_t h01 = packsplit(v.x, v.y, l01);
    uint32_t h23 = packsplit(v.z, v.w, l23);
    ((uint32_t*)hi)[i * 2]     = h01;
    ((uint32_t*)hi)[i * 2 + 1] = h23;
    ((uint32_t*)lo)[i * 2]     = l01;
    ((uint32_t*)lo)[i * 2 + 1] = l23;
}

// ---------------------------------------------------------------------------
// Fused weight transpose + split for all 4 weights (blockIdx.z selects W)
// ---------------------------------------------------------------------------
__global__ void __launch_bounds__(256) tsplit4_kernel(
    const float* __restrict__ Wq, const float* __restrict__ Wk,
    const float* __restrict__ Wv, const float* __restrict__ Wo,
    __nv_bfloat16* __restrict__ qh, __nv_bfloat16* __restrict__ ql,
    __nv_bfloat16* __restrict__ kh, __nv_bfloat16* __restrict__ kl,
    __nv_bfloat16* __restrict__ vh, __nv_bfloat16* __restrict__ vl,
    __nv_bfloat16* __restrict__ oh, __nv_bfloat16* __restrict__ ol)
{
    __shared__ float s[32][33];
    const float* W;
    __nv_bfloat16 *Th, *Tl;
    switch (blockIdx.z) {
        case 0:  W = Wq; Th = qh; Tl = ql; break;
        case 1:  W = Wk; Th = kh; Tl = kl; break;
        case 2:  W = Wv; Th = vh; Tl = vl; break;
        default: W = Wo; Th = oh; Tl = ol; break;
    }
    const int n0 = blockIdx.x * 32;
    const int k0 = blockIdx.y * 32;
    const int tx = threadIdx.x, ty = threadIdx.y;  // 32 x 8
#pragma unroll
    for (int r = 0; r < 32; r += 8)
        s[ty + r][tx] = W[(size_t)(k0 + ty + r) * cD + n0 + tx];
    __syncthreads();
#pragma unroll
    for (int r = 0; r < 32; r += 8) {
        float v = s[tx][ty + r];
        __nv_bfloat16 h = __float2bfloat16(v);
        __nv_bfloat16 l = __float2bfloat16(v - __bfloat162float(h));
        size_t o = (size_t)(n0 + ty + r) * cD + k0 + tx;
        Th[o] = h; Tl[o] = l;
    }
}

// ---------------------------------------------------------------------------
// Tensor-core causal flash attention (bf16 split, fp32 accum).
// __launch_bounds__(256, 2) -> 2 CTAs/SM (16 warps/SM).
// ---------------------------------------------------------------------------
constexpr int ALD = 72;                       // padded row length (bf16 elems)
constexpr int KV_TILE_B = 64 * ALD * 2;       // 9216 bytes
constexpr int KV_STB = 4 * KV_TILE_B;         // stage: Kh,Kl,Vh,Vl = 36864
constexpr int ATTN_SMEM = 2 * KV_STB;         // 73728
constexpr float CQ = 0.18033688011112042f;    // 0.125 * log2(e)

__global__ void __launch_bounds__(256, 2) attn_tc_kernel(
    const __nv_bfloat16* __restrict__ qh_g, const __nv_bfloat16* __restrict__ ql_g,
    const __nv_bfloat16* __restrict__ kh_g, const __nv_bfloat16* __restrict__ kl_g,
    const __nv_bfloat16* __restrict__ vh_g, const __nv_bfloat16* __restrict__ vl_g,
    __nv_bfloat16* __restrict__ ch_g, __nv_bfloat16* __restrict__ cl_g)
{
    const uint32_t sb0 = smem_to_u32(smem_raw);

    const int tid = threadIdx.x, wid = tid >> 5, lane = tid & 31;
    const int qt = (int)gridDim.x - 1 - (int)blockIdx.x;  // big tiles first
    const int h = blockIdx.y, b = blockIdx.z;
    const int qbase = qt * 128 + wid * 16;
    const size_t gb = (size_t)b * cS * cD + (size_t)h * cHD;

    const int vrow = tid >> 3, vseg = tid & 7;
    auto load_kv = [&](int t, int stage) {
        const int k0 = t * 64;
        const uint32_t s = sb0 + stage * KV_STB;
#pragma unroll
        for (int r = 0; r < 2; r++) {
            const int row = vrow + r * 32;
            const size_t g = gb + (size_t)(k0 + row) * cD + vseg * 8;
            const uint32_t so = (uint32_t)(row * ALD + vseg * 8) * 2;
            cp_async16(s + so,                kh_g + g);
            cp_async16(s + KV_TILE_B + so,    kl_g + g);
            cp_async16(s + 2 * KV_TILE_B + so, vh_g + g);
            cp_async16(s + 3 * KV_TILE_B + so, vl_g + g);
        }
    };
    load_kv(0, 0);
    CP_COMMIT();

    // Stage Q tile (hi/lo) into stage-1 region, extract fragments, then the
    // region is recycled for K/V stage 1 (guarded by the t=0 loop sync).
    {
        char* qp = smem_raw + KV_STB;
#pragma unroll
        for (int r = 0; r < 4; r++) {
            const int v = tid + r * 256;          // 0..1023
            const int row = v >> 3, seg = v & 7;
            const size_t g = gb + (size_t)(qt * 128 + row) * cD + seg * 8;
            const uint32_t so = (uint32_t)(row * ALD + seg * 8) * 2;
            *(uint4*)(qp + so)          = *(const uint4*)(qh_g + g);
            *(uint4*)(qp + 18432 + so)  = *(const uint4*)(ql_g + g);
        }
    }
    __syncthreads();
    uint32_t qfh[4][4], qfl[4][4];
    {
        const uint32_t qs = sb0 + KV_STB;
        const int rr = wid * 16 + (lane & 15);
        const int cc = (lane >> 4) * 8;
#pragma unroll
        for (int ks = 0; ks < 4; ks++) {
            const uint32_t off = (uint32_t)(rr * ALD + ks * 16 + cc) * 2;
            ldmx4(qfh[ks], qs + off);
            ldmx4(qfl[ks], qs + 18432 + off);
        }
    }

    float m0 = -1e30f, m1 = -1e30f, l0 = 0.f, l1 = 0.f;
    float out[8][4];
#pragma unroll
    for (int j = 0; j < 8; j++)
#pragma unroll
        for (int q = 0; q < 4; q++) out[j][q] = 0.f;

    const int ntiles = 2 * qt + 2;
    const int sub = lane >> 3, lr = lane & 7;
    const int row_lo = qbase + (lane >> 2);
    const int row_hi = row_lo + 8;

    for (int t = 0; t < ntiles; t++) {
        CP_WAIT0();
        __syncthreads();
        if (t + 1 < ntiles) { load_kv(t + 1, (t + 1) & 1); CP_COMMIT(); }

        const int k0 = t * 64;
        if (k0 <= qbase + 15) {          // any visible keys for this warp
            const uint32_t s = sb0 + (t & 1) * KV_STB;

            // ---- scores: S = Q @ K^T (3-term split) ----
            float sc[8][4];
#pragma unroll
            for (int j = 0; j < 8; j++) {
                sc[j][0] = 0.f; sc[j][1] = 0.f; sc[j][2] = 0.f; sc[j][3] = 0.f;
            }
#pragma unroll
            for (int ks = 0; ks < 4; ks++) {
#pragma unroll
                for (int g = 0; g < 4; g++) {
                    const uint32_t ko = (uint32_t)((g * 16 + (sub & 1) * 8 + lr) * ALD
                                                   + ks * 16 + (sub >> 1) * 8) * 2;
                    uint32_t bh[4], bl[4];
                    ldmx4(bh, s + ko);
                    ldmx4(bl, s + KV_TILE_B + ko);
                    mma16816(sc[2 * g],     qfh[ks], bh[0], bh[2]);
                    mma16816(sc[2 * g + 1], qfh[ks], bh[1], bh[3]);
                    mma16816(sc[2 * g],     qfh[ks], bl[0], bl[2]);
                    mma16816(sc[2 * g + 1], qfh[ks], bl[1], bl[3]);
                    mma16816(sc[2 * g],     qfl[ks], bh[0], bh[2]);
                    mma16816(sc[2 * g + 1], qfl[ks], bh[1], bh[3]);
                }
            }

            // ---- causal mask (diagonal tiles only) ----
            if (k0 + 63 > qbase) {
#pragma unroll
                for (int j = 0; j < 8; j++) {
                    const int c0 = k0 + j * 8 + (lane & 3) * 2;
                    if (c0     > row_lo) sc[j][0] = -1e30f;
                    if (c0 + 1 > row_lo) sc[j][1] = -1e30f;
                    if (c0     > row_hi) sc[j][2] = -1e30f;
                    if (c0 + 1 > row_hi) sc[j][3] = -1e30f;
                }
            }

            // ---- online softmax (raw-score domain, exp2 with CQ) ----
            float mx0 = -1e30f, mx1 = -1e30f;
#pragma unroll
            for (int j = 0; j < 8; j++) {
                mx0 = fmaxf(mx0, fmaxf(sc[j][0], sc[j][1]));
                mx1 = fmaxf(mx1, fmaxf(sc[j][2], sc[j][3]));
            }
            mx0 = fmaxf(mx0, __shfl_xor_sync(0xffffffffu, mx0, 1));
            mx0 = fmaxf(mx0, __shfl_xor_sync(0xffffffffu, mx0, 2));
            mx1 = fmaxf(mx1, __shfl_xor_sync(0xffffffffu, mx1, 1));
            mx1 = fmaxf(mx1, __shfl_xor_sync(0xffffffffu, mx1, 2));
            const float nm0 = fmaxf(m0, mx0), nm1 = fmaxf(m1, mx1);
            const float cr0 = exp2a((m0 - nm0) * CQ);
            const float cr1 = exp2a((m1 - nm1) * CQ);
            m0 = nm0; m1 = nm1;
            l0 *= cr0; l1 *= cr1;
#pragma unroll
            for (int j = 0; j < 8; j++) {
                out[j][0] *= cr0; out[j][1] *= cr0;
                out[j][2] *= cr1; out[j][3] *= cr1;
            }
#pragma unroll
            for (int j = 0; j < 8; j++) {
                sc[j][0] = exp2a((sc[j][0] - m0) * CQ);
                sc[j][1] = exp2a((sc[j][1] - m0) * CQ);
                sc[j][2] = exp2a((sc[j][2] - m1) * CQ);
                sc[j][3] = exp2a((sc[j][3] - m1) * CQ);
                l0 += sc[j][0] + sc[j][1];
                l1 += sc[j][2] + sc[j][3];
            }

            // ---- out += P @ V (3-term split, P split in registers) ----
#pragma unroll
            for (int t2 = 0; t2 < 4; t2++) {
                uint32_t ah[4], al[4];
                ah[0] = packsplit(sc[2 * t2][0],     sc[2 * t2][1],     al[0]);
                ah[1] = packsplit(sc[2 * t2][2],     sc[2 * t2][3],     al[1]);
                ah[2] = packsplit(sc[2 * t2 + 1][0], sc[2 * t2 + 1][1], al[2]);
                ah[3] = packsplit(sc[2 * t2 + 1][2], sc[2 * t2 + 1][3], al[3]);
#pragma unroll
                for (int g = 0; g < 4; g++) {
                    const uint32_t vo = (uint32_t)((t2 * 16 + (sub & 1) * 8 + lr) * ALD
                                                   + g * 16 + (sub >> 1) * 8) * 2;
                    uint32_t vhf[4], vlf[4];
                    ldmx4t(vhf, s + 2 * KV_TILE_B + vo);
                    ldmx4t(vlf, s + 3 * KV_TILE_B + vo);
                    mma16816(out[2 * g],     ah, vhf[0], vhf[1]);
                    mma16816(out[2 * g + 1], ah, vhf[2], vhf[3]);
                    mma16816(out[2 * g],     ah, vlf[0], vlf[1]);
                    mma16816(out[2 * g + 1], ah, vlf[2], vlf[3]);
                    mma16816(out[2 * g],     al, vhf[0], vhf[1]);
                    mma16816(out[2 * g + 1], al, vhf[2], vhf[3]);
                }
            }
        }
    }

    // ---- epilogue: normalize, split to bf16 hi/lo, store ctx ----
    l0 += __shfl_xor_sync(0xffffffffu, l0, 1);
    l0 += __shfl_xor_sync(0xffffffffu, l0, 2);
    l1 += __shfl_xor_sync(0xffffffffu, l1, 1);
    l1 += __shfl_xor_sync(0xffffffffu, l1, 2);
    const float inv0 = 1.f / l0, inv1 = 1.f / l1;

#pragma unroll
    for (int g = 0; g < 8; g++) {
        const int d = g * 8 + (lane & 3) * 2;
        const size_t o_lo = ((size_t)b * cS + row_lo) * cD + (size_t)h * cHD + d;
        const size_t o_hi = o_lo + (size_t)8 * cD;
        uint32_t lo32, hi32;
        hi32 = packsplit(out[g][0] * inv0, out[g][1] * inv0, lo32);
        *(uint32_t*)(ch_g + o_lo) = hi32;
        *(uint32_t*)(cl_g + o_lo) = lo32;
        hi32 = packsplit(out[g][2] * inv1, out[g][3] * inv1, lo32);
        *(uint32_t*)(ch_g + o_hi) = hi32;
        *(uint32_t*)(cl_g + o_hi) = lo32;
    }
}

// ---------------------------------------------------------------------------
// Launch
// ---------------------------------------------------------------------------
extern "C" void kernel_launch(void* const* d_in, const int* /*in_sizes*/, int /*n_in*/,
                              void* d_out, int /*out_size*/)
{
    const float* x  = (const float*)d_in[0];
    const float* Wq = (const float*)d_in[1];
    const float* Wk = (const float*)d_in[2];
    const float* Wv = (const float*)d_in[3];
    const float* Wo = (const float*)d_in[4];
    const float* bo = (const float*)d_in[5];
    float* out = (float*)d_out;

    __nv_bfloat16 *xh, *xl, *qh, *ql, *kh, *kl, *vh, *vl, *ch, *cl;
    __nv_bfloat16 *wqh, *wql, *wkh, *wkl, *wvh, *wvl, *woh, *wol;
    cudaGetSymbolAddress((void**)&xh, g_xh);
    cudaGetSymbolAddress((void**)&xl, g_xl);
    cudaGetSymbolAddress((void**)&qh, g_qh);
    cudaGetSymbolAddress((void**)&ql, g_ql);
    cudaGetSymbolAddress((void**)&kh, g_kh);
    cudaGetSymbolAddress((void**)&kl, g_kl);
    cudaGetSymbolAddress((void**)&vh, g_vh);
    cudaGetSymbolAddress((void**)&vl, g_vl);
    cudaGetSymbolAddress((void**)&ch, g_ch);
    cudaGetSymbolAddress((void**)&cl, g_cl);
    cudaGetSymbolAddress((void**)&wqh, g_Wqh);
    cudaGetSymbolAddress((void**)&wql, g_Wql);
    cudaGetSymbolAddress((void**)&wkh, g_Wkh);
    cudaGetSymbolAddress((void**)&wkl, g_Wkl);
    cudaGetSymbolAddress((void**)&wvh, g_Wvh);
    cudaGetSymbolAddress((void**)&wvl, g_Wvl);
    cudaGetSymbolAddress((void**)&woh, g_Woh);
    cudaGetSymbolAddress((void**)&wol, g_Wol);

    cudaFuncSetAttribute(gemm_qkv_kernel,
                         cudaFuncAttributeMaxDynamicSharedMemorySize, GEMM_SMEM);
    cudaFuncSetAttribute(gemm_out_kernel,
                         cudaFuncAttributeMaxDynamicSharedMemorySize, GEMM_SMEM);
    cudaFuncSetAttribute(attn_tc_kernel,
                         cudaFuncAttributeMaxDynamicSharedMemorySize, ATTN_SMEM);

    const int n4 = cM * cD / 4;
    split_kernel<<<(n4 + 255) / 256, 256>>>((const float4*)x, xh, xl, n4);

    dim3 tg(cD / 32, cD / 32, 4), tb(32, 8);
    tsplit4_kernel<<<tg, tb>>>(Wq, Wk, Wv, Wo,
                               wqh, wql, wkh, wkl, wvh, wvl, woh, wol);

    dim3 gq(24, cM / 128);  // (24, 32) — fused QKV
    gemm_qkv_kernel<<<gq, 256, GEMM_SMEM>>>(xh, xl, wqh, wql, wkh, wkl, wvh, wvl,
                                            qh, ql, kh, kl, vh, vl);

    dim3 ga(cS / 128, cH, cB);    // (16, 16, 2)
    attn_tc_kernel<<<ga, 256, ATTN_SMEM>>>(qh, ql, kh, kl, vh, vl, ch, cl);

    dim3 go(cD / 128, cM / 128);  // (8, 32)
    gemm_out_kernel<<<go, 256, GEMM_SMEM>>>(ch, cl, woh, wol, bo, out);
}